// round 1
// baseline (speedup 1.0000x reference)
#include <cuda_runtime.h>
#include <math.h>

// Problem constants
#define B_   8
#define CIN  512
#define S_   1024
#define NH   8
#define DH   64
#define ND   512            // NH*DH
#define MTOT (B_*S_)        // 8192

// Scratch (device globals — no allocations allowed)
__device__ float g_Q[(size_t)B_*NH*S_*DH];     // [b,h,s,d] 16MB
__device__ float g_K[(size_t)B_*NH*S_*DH];
__device__ float g_V[(size_t)B_*NH*S_*DH];
__device__ float g_attn[(size_t)MTOT*ND];      // [b*s, nh*d] 16MB

// ---------------------------------------------------------------------------
// Tiled SGEMM: C[m,n] = sum_k A(k,m)*W[k,n] (+bias, +residual / custom layouts)
// MODE 0: A is x viewed as [b][k][s] (k-major per batch); out -> Q/K/V [b,h,s,d]
// MODE 1: A is g_attn row-major [m][k]; out -> final [b, n, s] with residual x
// BM=128, BN=64, BK=16, 256 threads, 8x4 micro-tile.
// ---------------------------------------------------------------------------
#define BM 128
#define BN 64
#define BK 16

template<int MODE>
__global__ void __launch_bounds__(256)
gemm_kernel(const float* __restrict__ A, const float* __restrict__ W,
            const float* __restrict__ bias, const float* __restrict__ resid,
            float* __restrict__ out)
{
    __shared__ float As[BK * BM];      // MODE0: [k][m], MODE1: [m][k]
    __shared__ float Bs[BK][BN];

    const int tid = threadIdx.x;
    const int tx  = tid & 15;          // n-group (4 cols)
    const int ty  = tid >> 4;          // m-group (8 rows)
    const int m0  = blockIdx.y * BM;
    const int n0  = blockIdx.x * BN;
    const int b   = m0 >> 10;          // batch (MODE0); S_=1024 divides BM tiles
    const int s0  = m0 & 1023;

    float acc[8][4];
#pragma unroll
    for (int i = 0; i < 8; ++i)
#pragma unroll
        for (int j = 0; j < 4; ++j) acc[i][j] = 0.0f;

    for (int kt = 0; kt < CIN; kt += BK) {
        // --- load A tile ---
        if (MODE == 0) {
#pragma unroll
            for (int i = 0; i < 8; ++i) {
                int e = tid + i * 256;
                int r = e >> 7, c = e & 127;
                As[r * BM + c] = A[(size_t)(b * CIN + kt + r) * S_ + s0 + c];
            }
        } else {
#pragma unroll
            for (int i = 0; i < 2; ++i) {
                int e  = tid + i * 256;
                int r  = e >> 2;
                int c4 = (e & 3) * 4;
                float4 v = *(const float4*)&A[(size_t)(m0 + r) * ND + kt + c4];
                *(float4*)&As[r * BK + c4] = v;
            }
        }
        // --- load W tile 16x64 ---
        {
            int r  = tid >> 4;
            int c4 = (tid & 15) * 4;
            *(float4*)&Bs[r][c4] = *(const float4*)&W[(size_t)(kt + r) * ND + n0 + c4];
        }
        __syncthreads();

#pragma unroll
        for (int k = 0; k < BK; ++k) {
            float4 bv = *(const float4*)&Bs[k][tx * 4];
            float bvals[4] = {bv.x, bv.y, bv.z, bv.w};
            float avals[8];
#pragma unroll
            for (int i = 0; i < 8; ++i)
                avals[i] = (MODE == 0) ? As[k * BM + ty * 8 + i]
                                       : As[(ty * 8 + i) * BK + k];
#pragma unroll
            for (int i = 0; i < 8; ++i)
#pragma unroll
                for (int j = 0; j < 4; ++j)
                    acc[i][j] = fmaf(avals[i], bvals[j], acc[i][j]);
        }
        __syncthreads();
    }

    // --- epilogue ---
#pragma unroll
    for (int i = 0; i < 8; ++i) {
        int m  = m0 + ty * 8 + i;
        int mb = m >> 10;
        int s  = m & 1023;
#pragma unroll
        for (int j = 0; j < 4; ++j) {
            int n = n0 + tx * 4 + j;
            float val = acc[i][j] + bias[n];
            if (MODE == 0) {
                int h = n >> 6, d = n & 63;
                out[(((size_t)(mb * NH + h) * S_ + s) * DH) + d] = val;
            } else {
                size_t idx = (size_t)(mb * CIN + n) * S_ + s;
                out[idx] = val + resid[idx];
            }
        }
    }
}

// ---------------------------------------------------------------------------
// Flash attention: per block, 64 queries of one (b,h); loop over 16 key tiles
// of 64 keys. 128 threads; thread grid 16(q-groups of 4) x 8(k/d-groups of 8).
// Online softmax; P staged through the K smem buffer.
// Smem: Qs [d][q] stride 65 (scale folded in), Ks [d][k] stride 65 (reused as
// Ps [k][q] stride 65), Vs [k][d] stride 64.
// ---------------------------------------------------------------------------
#define QS_STRIDE 65
#define KS_STRIDE 65
#define VS_STRIDE 64
#define ATTN_SMEM ((64*QS_STRIDE + 64*KS_STRIDE + 64*VS_STRIDE) * (int)sizeof(float))

__global__ void __launch_bounds__(128)
attn_kernel(const float* __restrict__ Q, const float* __restrict__ K,
            const float* __restrict__ V, float* __restrict__ O)
{
    extern __shared__ float smem_dyn[];
    float* Qs = smem_dyn;                        // 64*65
    float* Ks = Qs + 64 * QS_STRIDE;             // 64*65 (also Ps)
    float* Vs = Ks + 64 * KS_STRIDE;             // 64*64

    const int tid = threadIdx.x;
    const int tk  = tid & 7;     // key/d group (8 wide)
    const int tq  = tid >> 3;    // query group (4 rows)
    const int bh  = blockIdx.y;  // 0..63
    const int q0g = blockIdx.x * 64;

    const float* Qbase = Q + ((size_t)bh * S_ + q0g) * DH;
    const float* Kbase = K + (size_t)bh * S_ * DH;
    const float* Vbase = V + (size_t)bh * S_ * DH;

    // Load Q tile transposed [d][q], fold in 1/sqrt(64)
    for (int idx = tid; idx < 64 * 64; idx += 128) {
        int q = idx >> 6, d = idx & 63;
        Qs[d * QS_STRIDE + q] = Qbase[idx] * 0.125f;
    }

    float m_run[4], l_run[4], o[4][8];
#pragma unroll
    for (int i = 0; i < 4; ++i) {
        m_run[i] = -1e30f;
        l_run[i] = 0.0f;
#pragma unroll
        for (int j = 0; j < 8; ++j) o[i][j] = 0.0f;
    }

    for (int kt = 0; kt < S_; kt += 64) {
        __syncthreads();   // previous tile consumers done (also covers Qs load)
        for (int idx = tid; idx < 64 * 64; idx += 128) {
            int r = idx >> 6, c = idx & 63;
            Ks[c * KS_STRIDE + r] = Kbase[kt * DH + idx];   // [d][k]
            Vs[idx]               = Vbase[kt * DH + idx];   // [k][d]
        }
        __syncthreads();

        // scores: sc[4q][8k]
        float sc[4][8];
#pragma unroll
        for (int i = 0; i < 4; ++i)
#pragma unroll
            for (int j = 0; j < 8; ++j) sc[i][j] = 0.0f;

#pragma unroll 4
        for (int d = 0; d < 64; ++d) {
            float qv[4], kv[8];
#pragma unroll
            for (int i = 0; i < 4; ++i) qv[i] = Qs[d * QS_STRIDE + tq * 4 + i];
#pragma unroll
            for (int j = 0; j < 8; ++j) kv[j] = Ks[d * KS_STRIDE + tk * 8 + j];
#pragma unroll
            for (int i = 0; i < 4; ++i)
#pragma unroll
                for (int j = 0; j < 8; ++j)
                    sc[i][j] = fmaf(qv[i], kv[j], sc[i][j]);
        }

        // online softmax (rows split across 8 consecutive lanes)
#pragma unroll
        for (int i = 0; i < 4; ++i) {
            float rm = sc[i][0];
#pragma unroll
            for (int j = 1; j < 8; ++j) rm = fmaxf(rm, sc[i][j]);
#pragma unroll
            for (int off = 4; off >= 1; off >>= 1)
                rm = fmaxf(rm, __shfl_xor_sync(0xffffffffu, rm, off));
            float mnew = fmaxf(m_run[i], rm);
            float corr = __expf(m_run[i] - mnew);
            float rs = 0.0f;
#pragma unroll
            for (int j = 0; j < 8; ++j) {
                float p = __expf(sc[i][j] - mnew);
                sc[i][j] = p;
                rs += p;
            }
#pragma unroll
            for (int off = 4; off >= 1; off >>= 1)
                rs += __shfl_xor_sync(0xffffffffu, rs, off);
            l_run[i] = l_run[i] * corr + rs;
            m_run[i] = mnew;
#pragma unroll
            for (int j = 0; j < 8; ++j) o[i][j] *= corr;
        }
        __syncthreads();   // all score reads of Ks done

        // stage P into Ks buffer as [k][q]
#pragma unroll
        for (int j = 0; j < 8; ++j)
#pragma unroll
            for (int i = 0; i < 4; ++i)
                Ks[(tk * 8 + j) * KS_STRIDE + tq * 4 + i] = sc[i][j];
        __syncthreads();

        // O += P @ V : o[4q][8d]
#pragma unroll 4
        for (int kk = 0; kk < 64; ++kk) {
            float pv[4], vv[8];
#pragma unroll
            for (int i = 0; i < 4; ++i) pv[i] = Ks[kk * KS_STRIDE + tq * 4 + i];
#pragma unroll
            for (int j = 0; j < 8; ++j) vv[j] = Vs[kk * VS_STRIDE + tk * 8 + j];
#pragma unroll
            for (int i = 0; i < 4; ++i)
#pragma unroll
                for (int j = 0; j < 8; ++j)
                    o[i][j] = fmaf(pv[i], vv[j], o[i][j]);
        }
    }

    // write attn output as [b*s][nh*d]
    const int b = bh >> 3, h = bh & 7;
#pragma unroll
    for (int i = 0; i < 4; ++i) {
        float inv = 1.0f / l_run[i];
        int q = q0g + tq * 4 + i;
        size_t row = (size_t)(b * S_ + q) * ND + h * DH + tk * 8;
#pragma unroll
        for (int j = 0; j < 8; ++j) O[row + j] = o[i][j] * inv;
    }
}

// ---------------------------------------------------------------------------
extern "C" void kernel_launch(void* const* d_in, const int* in_sizes, int n_in,
                              void* d_out, int out_size)
{
    (void)in_sizes; (void)n_in; (void)out_size;
    const float* x  = (const float*)d_in[0];
    const float* Wq = (const float*)d_in[1];
    const float* bq = (const float*)d_in[2];
    const float* Wk = (const float*)d_in[3];
    const float* bk = (const float*)d_in[4];
    const float* Wv = (const float*)d_in[5];
    const float* bv = (const float*)d_in[6];
    const float* Wo = (const float*)d_in[7];
    const float* bo = (const float*)d_in[8];
    float* out = (float*)d_out;

    float *Qp, *Kp, *Vp, *Ap;
    cudaGetSymbolAddress((void**)&Qp, g_Q);
    cudaGetSymbolAddress((void**)&Kp, g_K);
    cudaGetSymbolAddress((void**)&Vp, g_V);
    cudaGetSymbolAddress((void**)&Ap, g_attn);

    cudaFuncSetAttribute(attn_kernel,
                         cudaFuncAttributeMaxDynamicSharedMemorySize, ATTN_SMEM);

    dim3 gg(ND / BN, MTOT / BM);   // (8, 64)
    gemm_kernel<0><<<gg, 256>>>(x, Wq, bq, nullptr, Qp);
    gemm_kernel<0><<<gg, 256>>>(x, Wk, bk, nullptr, Kp);
    gemm_kernel<0><<<gg, 256>>>(x, Wv, bv, nullptr, Vp);

    attn_kernel<<<dim3(S_ / 64, B_ * NH), 128, ATTN_SMEM>>>(Qp, Kp, Vp, Ap);

    gemm_kernel<1><<<dim3(CIN / BN, MTOT / BM), 256>>>(Ap, Wo, bo, x, out);
}